// round 5
// baseline (speedup 1.0000x reference)
#include <cuda_runtime.h>
#include <cuda_fp16.h>
#include <math.h>

#define NN   100000
#define EE   1600000
#define ET   (EE + NN)     // edges + self loops
#define FIN  128
#define DD   64
#define HH   8
#define GG   64
#define NCLS 10
#define SLOPE 0.2f

#define NB_SCAN 98         // ceil(NN/1024)

// ---------------- scratch (device globals) ----------------
__device__ __half2 g_projh[NN * 32];     // h = I @ W, fp16 packed (1 line/row)
__device__ float g_act [NN * DD];        // normalized layer output (layers 1,2)
__device__ float g_als [NN * HH];
__device__ float g_ald [NN * HH];
__device__ int   g_rowptr[NN + 1];
__device__ int   g_col [ET];
__device__ int   g_cnti[NN];
__device__ int   g_rank[ET];
__device__ int   g_bsum[NB_SCAN];
__device__ int   g_boff[NB_SCAN];
__device__ float g_sums[GG * DD];
__device__ float g_cnt [GG];

// ---------------- zero aux ----------------
__global__ void zero_aux_kernel() {
    int i = blockIdx.x * blockDim.x + threadIdx.x;
    if (i < NN) g_cnti[i] = 0;
    if (i < GG * DD) g_sums[i] = 0.f;
    if (i < GG)      g_cnt[i]  = 0.f;
}

// ---------------- CSR build ----------------
// hist also records each edge's within-dst rank (atomic's return value),
// making the scatter pass atomic-free.
__global__ void hist_kernel(const int* __restrict__ ei) {
    int i = blockIdx.x * blockDim.x + threadIdx.x;
    if (i >= ET) return;
    int dst = (i < EE) ? ei[EE + i] : (i - EE);
    g_rank[i] = atomicAdd(&g_cnti[dst], 1);
}

__global__ void scan1_kernel() {
    __shared__ int sd[256];
    const int t = threadIdx.x;
    const int base = blockIdx.x * 1024 + t * 4;
    int v[4];
#pragma unroll
    for (int i = 0; i < 4; i++) {
        int idx = base + i;
        v[i] = (idx < NN) ? g_cnti[idx] : 0;
    }
    int pre[4];
    pre[0] = 0; pre[1] = v[0]; pre[2] = v[0] + v[1]; pre[3] = v[0] + v[1] + v[2];
    int sum = pre[3] + v[3];
    sd[t] = sum;
    __syncthreads();
    for (int off = 1; off < 256; off <<= 1) {
        int x = 0;
        if (t >= off) x = sd[t - off];
        __syncthreads();
        if (t >= off) sd[t] += x;
        __syncthreads();
    }
    int toff = sd[t] - sum;
#pragma unroll
    for (int i = 0; i < 4; i++) {
        int idx = base + i;
        if (idx < NN) g_rowptr[idx] = toff + pre[i];
    }
    if (t == 255) g_bsum[blockIdx.x] = sd[255];
}

__global__ void scan2_kernel() {
    __shared__ int sd[128];
    const int t = threadIdx.x;
    int v = (t < NB_SCAN) ? g_bsum[t] : 0;
    sd[t] = v;
    __syncthreads();
    for (int off = 1; off < 128; off <<= 1) {
        int x = 0;
        if (t >= off) x = sd[t - off];
        __syncthreads();
        if (t >= off) sd[t] += x;
        __syncthreads();
    }
    if (t < NB_SCAN) g_boff[t] = sd[t] - v;
    if (t == NB_SCAN - 1) g_rowptr[NN] = sd[t];
}

__global__ void scan3_kernel() {
    int i = blockIdx.x * blockDim.x + threadIdx.x;
    if (i < NN) g_rowptr[i] += g_boff[i >> 10];
}

__global__ void scatter_kernel(const int* __restrict__ ei) {
    int i = blockIdx.x * blockDim.x + threadIdx.x;
    if (i >= ET) return;
    int src, dst;
    if (i < EE) { src = ei[i]; dst = ei[EE + i]; }
    else        { src = dst = i - EE; }
    g_col[g_rowptr[dst] + g_rank[i]] = src;
}

// ---------------- register-tiled GEMM + attention logits ----------------
// 256 threads, tile 32 nodes x 64 cols, K chunks of 64; thread: 2 nodes x 4 cols.
// Writes g_projh (fp16) + g_als/g_ald (fp32, from fp32 accumulators).
template<int K, bool FIRST>
__global__ void gemm_al_kernel(const float* __restrict__ I,
                               const float* __restrict__ W,
                               const float* __restrict__ a_src,
                               const float* __restrict__ a_dst,
                               const float* __restrict__ prev_bias) {
    __shared__ float xs[32][68];
    __shared__ float Wsm[64][64];
    const int t  = threadIdx.x;
    const int tx = t & 15;
    const int ty = t >> 4;
    const int node0 = blockIdx.x * 32;

    float acc[2][4] = {{0.f,0.f,0.f,0.f},{0.f,0.f,0.f,0.f}};
    const int n0 = 2 * ty, n1 = 2 * ty + 1;

    for (int kc = 0; kc < K; kc += 64) {
#pragma unroll
        for (int it = 0; it < 2; it++) {
            int fid  = t + it * 256;
            int node = fid >> 4;
            int kq   = (fid & 15) * 4;
            float4 v;
            if (FIRST) {
                v = *(const float4*)&I[(size_t)(node0 + node) * K + kc + kq];
            } else {
                v = *(const float4*)&g_act[(size_t)(node0 + node) * K + kc + kq];
                v.x += prev_bias[kc + kq    ];
                v.y += prev_bias[kc + kq + 1];
                v.z += prev_bias[kc + kq + 2];
                v.w += prev_bias[kc + kq + 3];
                v.x = v.x > 0.f ? v.x : expm1f(v.x);
                v.y = v.y > 0.f ? v.y : expm1f(v.y);
                v.z = v.z > 0.f ? v.z : expm1f(v.z);
                v.w = v.w > 0.f ? v.w : expm1f(v.w);
            }
            *(float4*)&xs[node][kq] = v;
        }
#pragma unroll
        for (int it = 0; it < 4; it++) {
            int fid = t + it * 256;
            int kk  = fid >> 4;
            int cq  = (fid & 15) * 4;
            *(float4*)&Wsm[kk][cq] = *(const float4*)&W[(size_t)(kc + kk) * DD + cq];
        }
        __syncthreads();
#pragma unroll
        for (int k = 0; k < 64; k++) {
            float xv0 = xs[n0][k];
            float xv1 = xs[n1][k];
            float4 wv = *(const float4*)&Wsm[k][tx * 4];
            acc[0][0] = fmaf(xv0, wv.x, acc[0][0]);
            acc[0][1] = fmaf(xv0, wv.y, acc[0][1]);
            acc[0][2] = fmaf(xv0, wv.z, acc[0][2]);
            acc[0][3] = fmaf(xv0, wv.w, acc[0][3]);
            acc[1][0] = fmaf(xv1, wv.x, acc[1][0]);
            acc[1][1] = fmaf(xv1, wv.y, acc[1][1]);
            acc[1][2] = fmaf(xv1, wv.z, acc[1][2]);
            acc[1][3] = fmaf(xv1, wv.w, acc[1][3]);
        }
        __syncthreads();
    }

    const int gn0 = node0 + n0, gn1 = node0 + n1;
    // fp16 proj rows (one 128B line per node row)
    __half2 h00 = __floats2half2_rn(acc[0][0], acc[0][1]);
    __half2 h01 = __floats2half2_rn(acc[0][2], acc[0][3]);
    __half2 h10 = __floats2half2_rn(acc[1][0], acc[1][1]);
    __half2 h11 = __floats2half2_rn(acc[1][2], acc[1][3]);
    g_projh[(size_t)gn0 * 32 + tx * 2    ] = h00;
    g_projh[(size_t)gn0 * 32 + tx * 2 + 1] = h01;
    g_projh[(size_t)gn1 * 32 + tx * 2    ] = h10;
    g_projh[(size_t)gn1 * 32 + tx * 2 + 1] = h11;

    float s0 = 0.f, d0 = 0.f, s1 = 0.f, d1 = 0.f;
#pragma unroll
    for (int j = 0; j < 4; j++) {
        int c = tx * 4 + j;
        float asv = a_src[c], adv = a_dst[c];
        s0 = fmaf(acc[0][j], asv, s0);
        d0 = fmaf(acc[0][j], adv, d0);
        s1 = fmaf(acc[1][j], asv, s1);
        d1 = fmaf(acc[1][j], adv, d1);
    }
    s0 += __shfl_xor_sync(0xffffffffu, s0, 1);
    d0 += __shfl_xor_sync(0xffffffffu, d0, 1);
    s1 += __shfl_xor_sync(0xffffffffu, s1, 1);
    d1 += __shfl_xor_sync(0xffffffffu, d1, 1);
    if ((tx & 1) == 0) {
        int h = tx >> 1;
        g_als[gn0 * HH + h] = s0;
        g_ald[gn0 * HH + h] = d0;
        g_als[gn1 * HH + h] = s1;
        g_ald[gn1 * HH + h] = d1;
    }
}

// ---------------- CSR edge kernel: warp per dst, no atomics ----------------
// POOL=true (layer 3): skip writing act; apply elu(.+b3) and pool directly.
#define EW 8
template<bool POOL>
__global__ void edge_csr_kernel(const int* __restrict__ batch,
                                const float* __restrict__ b3) {
    __shared__ int   ss[EW][32];
    __shared__ float ws[EW][32][9];
    const int wl   = threadIdx.x >> 5;
    const int lane = threadIdx.x & 31;
    const int n = blockIdx.x * EW + wl;
    if (n >= NN) return;
    const int rs = g_rowptr[n], re = g_rowptr[n + 1];

    const float4 ad0 = *(const float4*)&g_ald[n * HH];
    const float4 ad1 = *(const float4*)&g_ald[n * HH + 4];

    float2 acc = make_float2(0.f, 0.f);
    float dn = 0.f;
    const int h = lane >> 2;

    for (int base = rs; base < re; base += 32) {
        const int e = base + lane;
        if (e < re) {
            int src = g_col[e];
            ss[wl][lane] = src;
            float4 s0 = *(const float4*)&g_als[src * HH];
            float4 s1 = *(const float4*)&g_als[src * HH + 4];
            float ev[8] = { s0.x + ad0.x, s0.y + ad0.y, s0.z + ad0.z, s0.w + ad0.w,
                            s1.x + ad1.x, s1.y + ad1.y, s1.z + ad1.z, s1.w + ad1.w };
#pragma unroll
            for (int hh = 0; hh < 8; hh++) {
                float v = ev[hh] > 0.f ? ev[hh] : SLOPE * ev[hh];
                ws[wl][lane][hh] = __expf(v);
            }
        }
        __syncwarp();
        const int cnt = min(32, re - base);
#pragma unroll 8
        for (int j = 0; j < cnt; j++) {
            int   sj = ss[wl][j];
            float wj = ws[wl][j][h];
            dn += wj;
            float2 p = __half22float2(g_projh[(size_t)sj * 32 + lane]);
            acc.x = fmaf(p.x, wj, acc.x);
            acc.y = fmaf(p.y, wj, acc.y);
        }
        __syncwarp();
    }
    const float inv = 1.f / dn;
    if (POOL) {
        float v0 = acc.x * inv + b3[2 * lane];
        float v1 = acc.y * inv + b3[2 * lane + 1];
        v0 = v0 > 0.f ? v0 : expm1f(v0);
        v1 = v1 > 0.f ? v1 : expm1f(v1);
        int g = batch[n];
        atomicAdd(&g_sums[g * DD + 2 * lane],     v0);
        atomicAdd(&g_sums[g * DD + 2 * lane + 1], v1);
        if (lane == 0) atomicAdd(&g_cnt[g], 1.0f);
    } else {
        *(float2*)&g_act[(size_t)n * DD + 2 * lane] =
            make_float2(acc.x * inv, acc.y * inv);
    }
}

// ---------------- final linear ----------------
__global__ void final_kernel(const float* __restrict__ lin_W,
                             const float* __restrict__ lin_b,
                             float* __restrict__ out) {
    int t = threadIdx.x;
    if (t >= GG * NCLS) return;
    int g = t / NCLS;
    int c = t % NCLS;
    float cnt = fmaxf(g_cnt[g], 1.0f);
    float acc = lin_b[c];
#pragma unroll
    for (int d = 0; d < DD; d++)
        acc = fmaf(g_sums[g * DD + d] / cnt, lin_W[d * NCLS + c], acc);
    out[g * NCLS + c] = acc;
}

// ---------------- launch ----------------
extern "C" void kernel_launch(void* const* d_in, const int* in_sizes, int n_in,
                              void* d_out, int out_size) {
    const float* x      = (const float*)d_in[0];
    const int*   ei     = (const int*)  d_in[1];
    const int*   batch  = (const int*)  d_in[2];
    const float* W1     = (const float*)d_in[3];
    const float* a1s    = (const float*)d_in[4];
    const float* a1d    = (const float*)d_in[5];
    const float* b1     = (const float*)d_in[6];
    const float* W2     = (const float*)d_in[7];
    const float* a2s    = (const float*)d_in[8];
    const float* a2d    = (const float*)d_in[9];
    const float* b2     = (const float*)d_in[10];
    const float* W3     = (const float*)d_in[11];
    const float* a3s    = (const float*)d_in[12];
    const float* a3d    = (const float*)d_in[13];
    const float* b3     = (const float*)d_in[14];
    const float* lin_W  = (const float*)d_in[15];
    const float* lin_b  = (const float*)d_in[16];
    float* out = (float*)d_out;

    const int ngrid = NN / 32;
    const int egrid = (NN + EW - 1) / EW;
    const int etg   = (ET + 255) / 256;

    // ---- CSR build ----
    zero_aux_kernel<<<(NN + 255) / 256, 256>>>();
    hist_kernel<<<etg, 256>>>(ei);
    scan1_kernel<<<NB_SCAN, 256>>>();
    scan2_kernel<<<1, 128>>>();
    scan3_kernel<<<(NN + 255) / 256, 256>>>();
    scatter_kernel<<<etg, 256>>>(ei);

    // ---- layer 1 ----
    gemm_al_kernel<FIN, true><<<ngrid, 256>>>(x, W1, a1s, a1d, nullptr);
    edge_csr_kernel<false><<<egrid, 256>>>(nullptr, nullptr);

    // ---- layer 2 ----
    gemm_al_kernel<DD, false><<<ngrid, 256>>>(nullptr, W2, a2s, a2d, b1);
    edge_csr_kernel<false><<<egrid, 256>>>(nullptr, nullptr);

    // ---- layer 3 (pool fused) ----
    gemm_al_kernel<DD, false><<<ngrid, 256>>>(nullptr, W3, a3s, a3d, b2);
    edge_csr_kernel<true><<<egrid, 256>>>(batch, b3);

    // ---- classify ----
    final_kernel<<<1, GG * NCLS>>>(lin_W, lin_b, out);
}